// round 6
// baseline (speedup 1.0000x reference)
#include <cuda_runtime.h>
#include <cstdint>
#include <math.h>

// Problem dims (fixed by reference setup_inputs)
#define BB 4
#define TT 4096
#define HH 1024
#define M_TOTAL (BB*TT)      // 16384
#define NCHUNK 64
#define CHUNK (TT/NCHUNK)    // 64

// Scratch (allocation-free rule: __device__ globals)
__device__ float g_normed[(size_t)M_TOTAL*HH];
__device__ float g_z[(size_t)M_TOTAL*HH];
__device__ float g_c[(size_t)M_TOTAL*HH];
__device__ float g_Wr[(size_t)2*HH*HH];     // tf32-rounded [Wg; Wc]
__device__ float g_P[BB*NCHUNK*HH];
__device__ float g_S[BB*NCHUNK*HH];
__device__ float g_hin[BB*NCHUNK*HH];

__device__ __forceinline__ unsigned f2tf32(float f) {
    unsigned u;
    asm volatile("cvt.rna.tf32.f32 %0, %1;" : "=r"(u) : "f"(f));
    return u;
}
__device__ __forceinline__ uint32_t smem_u32(const void* p) {
    uint32_t a;
    asm("{ .reg .u64 t; cvta.to.shared.u64 t, %1; cvt.u32.u64 %0, t; }" : "=r"(a) : "l"(p));
    return a;
}
__device__ __forceinline__ void cp16(uint32_t dst, const void* src) {
    asm volatile("cp.async.cg.shared.global [%0], [%1], 16;" :: "r"(dst), "l"(src));
}

// ---------------------------------------------------------------------------
// Kernel 0: pre-round Wg/Wc to tf32 (round-to-nearest) into g_Wr
// ---------------------------------------------------------------------------
__global__ void roundW_kernel(const float* __restrict__ Wg,
                              const float* __restrict__ Wc) {
    int i = blockIdx.x * blockDim.x + threadIdx.x;   // over 2*HH*HH/4
    int half = HH * HH / 4;
    const float4* src = (i < half) ? (const float4*)Wg : (const float4*)Wc;
    float4 v = src[(i < half) ? i : (i - half)];
    uint4 o;
    o.x = f2tf32(v.x); o.y = f2tf32(v.y); o.z = f2tf32(v.z); o.w = f2tf32(v.w);
    ((uint4*)g_Wr)[i] = o;
}

// ---------------------------------------------------------------------------
// Kernel 1: LayerNorm -> tf32-rounded normed
// ---------------------------------------------------------------------------
__global__ void ln_kernel(const float* __restrict__ x,
                          const float* __restrict__ gamma,
                          const float* __restrict__ beta) {
    int row = blockIdx.x;
    int tid = threadIdx.x;      // 256
    const float4* xr = (const float4*)(x + (size_t)row * HH);
    float4 v = xr[tid];
    float s  = v.x + v.y + v.z + v.w;
    float s2 = v.x*v.x + v.y*v.y + v.z*v.z + v.w*v.w;
    #pragma unroll
    for (int o = 16; o > 0; o >>= 1) {
        s  += __shfl_xor_sync(0xFFFFFFFFu, s,  o);
        s2 += __shfl_xor_sync(0xFFFFFFFFu, s2, o);
    }
    __shared__ float ss[8], ss2[8];
    int w = tid >> 5, l = tid & 31;
    if (l == 0) { ss[w] = s; ss2[w] = s2; }
    __syncthreads();
    if (w == 0) {
        float a  = (l < 8) ? ss[l]  : 0.f;
        float a2 = (l < 8) ? ss2[l] : 0.f;
        #pragma unroll
        for (int o = 4; o > 0; o >>= 1) {
            a  += __shfl_xor_sync(0xFFFFFFFFu, a,  o);
            a2 += __shfl_xor_sync(0xFFFFFFFFu, a2, o);
        }
        if (l == 0) { ss[0] = a; ss2[0] = a2; }
    }
    __syncthreads();
    float mu  = ss[0] * (1.f / HH);
    float var = ss2[0] * (1.f / HH) - mu * mu;
    float rs  = rsqrtf(var + 1e-5f);
    float4 g  = ((const float4*)gamma)[tid];
    float4 bt = ((const float4*)beta)[tid];
    uint4 o;
    o.x = f2tf32((v.x - mu) * rs * g.x + bt.x);
    o.y = f2tf32((v.y - mu) * rs * g.y + bt.y);
    o.z = f2tf32((v.z - mu) * rs * g.z + bt.z);
    o.w = f2tf32((v.w - mu) * rs * g.w + bt.w);
    ((uint4*)g_normed)[(size_t)row * (HH/4) + tid] = o;
}

// ---------------------------------------------------------------------------
// Kernel 2: tf32 mma.sync GEMM, cp.async 3-stage pipeline.
// Block tile 256x128, BK=32, 256 threads (8 warps), warp tile 64x64
// (4 M-warps x 2 N-warps) -> 1.0 LDS.32 per mma.
// Logical N = 2048: bn<8 -> Wg+sigmoid -> g_z, bn>=8 -> Wc -> g_c.
// ---------------------------------------------------------------------------
#define BM 256
#define BN 128
#define BK 32
#define STAGES 3
#define SPAD 4
#define SSTR (BK + SPAD)                 // 36 floats; row stride 144B (16B-mult)
#define A_STAGE (BM*SSTR)                // 9216 floats per A stage
#define B_STAGE (BN*SSTR)                // 4608 floats per B stage
#define GEMM_SMEM (STAGES*(A_STAGE+B_STAGE)*4)   // 165888 B

__global__ __launch_bounds__(256, 1) void gemm_kernel(
    const float* __restrict__ bg, const float* __restrict__ bc)
{
    extern __shared__ float sm[];
    float* sA = sm;
    float* sB = sm + STAGES * A_STAGE;
    uint32_t sA_u = smem_u32(sA);
    uint32_t sB_u = smem_u32(sB);

    int tid = threadIdx.x;               // 256
    int warp = tid >> 5, lane = tid & 31;
    int bn = blockIdx.x;                 // 0..15 (fast -> wave shares A in L2)
    int bm = blockIdx.y;                 // 0..63
    int wm = (warp & 3) * 64;            // 4 M-warps
    int wn = (warp >> 2) * 64;           // 2 N-warps

    bool isGate = (bn < 8);
    size_t woff = isGate ? 0 : (size_t)HH * HH;
    int nbase = (bn & 7) * BN;
    size_t arow = (size_t)bm * BM;

    const float* Asrc0 = g_normed + arow * HH;
    const float* Bsrc0 = g_Wr + woff + (size_t)nbase * HH;

    float acc[4][8][4];
    #pragma unroll
    for (int i = 0; i < 4; i++)
        #pragma unroll
        for (int j = 0; j < 8; j++)
            #pragma unroll
            for (int q = 0; q < 4; q++) acc[i][j][q] = 0.f;

    // A: 256x32 = 2048 16B-chunks / 256 thr = 8 each; B: 128x32 = 1024 -> 4 each
    int lr[8], lc[8];
    #pragma unroll
    for (int q = 0; q < 8; q++) {
        int f = tid + q * 256;
        lr[q] = f >> 3;
        lc[q] = (f & 7) << 2;
    }

    #define LOAD_STAGE(s, k0) do { \
        uint32_t abase = sA_u + (uint32_t)(s) * A_STAGE * 4; \
        uint32_t bbase = sB_u + (uint32_t)(s) * B_STAGE * 4; \
        _Pragma("unroll") \
        for (int q = 0; q < 8; q++) \
            cp16(abase + (uint32_t)(lr[q] * SSTR + lc[q]) * 4, \
                 Asrc0 + (size_t)lr[q] * HH + (k0) + lc[q]); \
        _Pragma("unroll") \
        for (int q = 0; q < 4; q++) \
            cp16(bbase + (uint32_t)(lr[q] * SSTR + lc[q]) * 4, \
                 Bsrc0 + (size_t)lr[q] * HH + (k0) + lc[q]); \
    } while (0)

    LOAD_STAGE(0, 0);
    asm volatile("cp.async.commit_group;");
    LOAD_STAGE(1, BK);
    asm volatile("cp.async.commit_group;");

    const int NK = HH / BK;              // 32
    for (int i = 0; i < NK; i++) {
        int s = i % STAGES;
        asm volatile("cp.async.wait_group 1;");
        __syncthreads();
        if (i + 2 < NK) {
            int s2 = (i + 2) % STAGES;
            LOAD_STAGE(s2, (i + 2) * BK);
        }
        asm volatile("cp.async.commit_group;");

        const float* As = sA + s * A_STAGE;
        const float* Bs = sB + s * B_STAGE;
        int r = lane >> 2;
        #pragma unroll
        for (int kk = 0; kk < 4; kk++) {
            int kb = kk * 8 + (lane & 3);
            unsigned af[4][4], bf[8][2];
            #pragma unroll
            for (int ii = 0; ii < 4; ii++) {
                int m0 = wm + ii * 16 + r;
                af[ii][0] = __float_as_uint(As[m0 * SSTR + kb]);
                af[ii][1] = __float_as_uint(As[(m0 + 8) * SSTR + kb]);
                af[ii][2] = __float_as_uint(As[m0 * SSTR + kb + 4]);
                af[ii][3] = __float_as_uint(As[(m0 + 8) * SSTR + kb + 4]);
            }
            #pragma unroll
            for (int j = 0; j < 8; j++) {
                int n0 = wn + j * 8 + r;
                bf[j][0] = __float_as_uint(Bs[n0 * SSTR + kb]);
                bf[j][1] = __float_as_uint(Bs[n0 * SSTR + kb + 4]);
            }
            #pragma unroll
            for (int ii = 0; ii < 4; ii++)
                #pragma unroll
                for (int j = 0; j < 8; j++)
                    asm volatile(
                        "mma.sync.aligned.m16n8k8.row.col.f32.tf32.tf32.f32 "
                        "{%0,%1,%2,%3},{%4,%5,%6,%7},{%8,%9},{%0,%1,%2,%3};"
                        : "+f"(acc[ii][j][0]), "+f"(acc[ii][j][1]),
                          "+f"(acc[ii][j][2]), "+f"(acc[ii][j][3])
                        : "r"(af[ii][0]), "r"(af[ii][1]), "r"(af[ii][2]), "r"(af[ii][3]),
                          "r"(bf[j][0]), "r"(bf[j][1]));
        }
        __syncthreads();
    }

    // Epilogue: +bias, optional sigmoid, write z or c
    int r  = lane >> 2;
    int cq = (lane & 3) * 2;
    const float* bias = isGate ? bg : bc;
    float* outp = isGate ? g_z : g_c;
    #pragma unroll
    for (int ii = 0; ii < 4; ii++) {
        #pragma unroll
        for (int j = 0; j < 8; j++) {
            int m0 = bm * BM + wm + ii * 16 + r;
            int n0 = nbase + wn + j * 8 + cq;
            float b0 = bias[n0], b1 = bias[n0 + 1];
            float v0 = acc[ii][j][0] + b0;
            float v1 = acc[ii][j][1] + b1;
            float v2 = acc[ii][j][2] + b0;
            float v3 = acc[ii][j][3] + b1;
            if (isGate) {
                v0 = 1.f / (1.f + __expf(-v0));
                v1 = 1.f / (1.f + __expf(-v1));
                v2 = 1.f / (1.f + __expf(-v2));
                v3 = 1.f / (1.f + __expf(-v3));
            }
            *(float2*)(outp + (size_t)m0 * HH + n0)       = make_float2(v0, v1);
            *(float2*)(outp + (size_t)(m0 + 8) * HH + n0) = make_float2(v2, v3);
        }
    }
}

// ---------------------------------------------------------------------------
// Scan phase A: per-(b, chunk, hid) aggregates (P = prod(1-z), S = scan from 0)
// ---------------------------------------------------------------------------
__global__ void scanA_kernel() {
    int g   = blockIdx.x * blockDim.x + threadIdx.x;   // BB*NCHUNK*HH threads
    int hid = g % HH;
    int ck  = (g / HH) % NCHUNK;
    int b   = g / (HH * NCHUNK);
    size_t base = ((size_t)(b * TT + ck * CHUNK)) * HH + hid;
    float P = 1.f, S = 0.f;
    #pragma unroll 8
    for (int t = 0; t < CHUNK; t++) {
        float z = g_z[base + (size_t)t * HH];
        float c = g_c[base + (size_t)t * HH];
        float a = 1.f - z;
        S = a * S + z * c;
        P = a * P;
    }
    g_P[g] = P;
    g_S[g] = S;
}

// ---------------------------------------------------------------------------
// Scan phase B: parallel Kogge-Stone over 64 chunk aggregates per (b,hid).
// One warp per (b,hid); each lane composes 2 chunks, then 5-step shfl scan.
// ---------------------------------------------------------------------------
__global__ void scanB_kernel() {
    int gt   = blockIdx.x * blockDim.x + threadIdx.x;
    int lane = gt & 31;
    int wg   = gt >> 5;                 // 0..BB*HH-1
    int hid  = wg & (HH - 1);
    int b    = wg >> 10;                // HH = 1024
    int k0   = 2 * lane;
    size_t i0 = ((size_t)(b * NCHUNK + k0)) * HH + hid;
    float P0 = g_P[i0],      S0 = g_S[i0];
    float P1 = g_P[i0 + HH], S1 = g_S[i0 + HH];
    float cP = P1 * P0;
    float cS = P1 * S0 + S1;
    #pragma unroll
    for (int d = 1; d < 32; d <<= 1) {
        float pP = __shfl_up_sync(0xFFFFFFFFu, cP, d);
        float pS = __shfl_up_sync(0xFFFFFFFFu, cS, d);
        if (lane >= d) { cS = cP * pS + cS; cP = cP * pP; }
    }
    float eS = __shfl_up_sync(0xFFFFFFFFu, cS, 1);
    if (lane == 0) eS = 0.f;
    g_hin[i0]      = eS;
    g_hin[i0 + HH] = P0 * eS + S0;
}

// ---------------------------------------------------------------------------
// Scan phase C: re-run each chunk with the correct h_in, fuse residual +x
// ---------------------------------------------------------------------------
__global__ void scanC_kernel(const float* __restrict__ x, float* __restrict__ out) {
    int g   = blockIdx.x * blockDim.x + threadIdx.x;
    int hid = g % HH;
    int ck  = (g / HH) % NCHUNK;
    int b   = g / (HH * NCHUNK);
    size_t base = ((size_t)(b * TT + ck * CHUNK)) * HH + hid;
    float h = g_hin[g];
    #pragma unroll 8
    for (int t = 0; t < CHUNK; t++) {
        size_t idx = base + (size_t)t * HH;
        float z = g_z[idx];
        float c = g_c[idx];
        h = (1.f - z) * h + z * c;
        out[idx] = h + x[idx];
    }
}

// ---------------------------------------------------------------------------
extern "C" void kernel_launch(void* const* d_in, const int* in_sizes, int n_in,
                              void* d_out, int out_size) {
    const float* x     = (const float*)d_in[0];
    const float* gamma = (const float*)d_in[1];
    const float* beta  = (const float*)d_in[2];
    const float* Wg    = (const float*)d_in[3];
    const float* bg    = (const float*)d_in[4];
    const float* Wc    = (const float*)d_in[5];
    const float* bc    = (const float*)d_in[6];
    float* out = (float*)d_out;

    roundW_kernel<<<(2 * HH * HH / 4) / 256, 256>>>(Wg, Wc);
    ln_kernel<<<M_TOTAL, 256>>>(x, gamma, beta);

    cudaFuncSetAttribute(gemm_kernel,
                         cudaFuncAttributeMaxDynamicSharedMemorySize, GEMM_SMEM);
    dim3 ggrid(2 * HH / BN, M_TOTAL / BM);   // (16, 64)
    gemm_kernel<<<ggrid, 256, GEMM_SMEM>>>(bg, bc);

    scanA_kernel<<<(BB * NCHUNK * HH) / 256, 256>>>();
    scanB_kernel<<<(BB * HH * 32) / 256, 256>>>();
    scanC_kernel<<<(BB * NCHUNK * HH) / 256, 256>>>(x, out);
}

// round 7
// speedup vs baseline: 1.6753x; 1.6753x over previous
#include <cuda_runtime.h>
#include <cuda_fp16.h>
#include <cstdint>
#include <math.h>

// Problem dims (fixed by reference setup_inputs)
#define BB 4
#define TT 4096
#define HH 1024
#define M_TOTAL (BB*TT)      // 16384
#define NCHUNK 64
#define CHUNK (TT/NCHUNK)    // 64

// Scratch (allocation-free rule: __device__ globals)
__device__ __half g_normh[(size_t)M_TOTAL*HH];   // fp16 LN output (32MB)
__device__ __half g_Wh[(size_t)2*HH*HH];         // fp16 [Wg; Wc] (4MB)
__device__ float g_z[(size_t)M_TOTAL*HH];
__device__ float g_c[(size_t)M_TOTAL*HH];
__device__ float g_P[BB*NCHUNK*HH];
__device__ float g_S[BB*NCHUNK*HH];
__device__ float g_hin[BB*NCHUNK*HH];

__device__ __forceinline__ uint32_t smem_u32(const void* p) {
    uint32_t a;
    asm("{ .reg .u64 t; cvta.to.shared.u64 t, %1; cvt.u32.u64 %0, t; }" : "=r"(a) : "l"(p));
    return a;
}
__device__ __forceinline__ void cp16(uint32_t dst, const void* src) {
    asm volatile("cp.async.cg.shared.global [%0], [%1], 16;" :: "r"(dst), "l"(src));
}

// ---------------------------------------------------------------------------
// Kernel 0: convert Wg/Wc to fp16 into g_Wh
// ---------------------------------------------------------------------------
__global__ void halfW_kernel(const float* __restrict__ Wg,
                             const float* __restrict__ Wc) {
    int i = blockIdx.x * blockDim.x + threadIdx.x;   // over 2*HH*HH/4
    int half_n = HH * HH / 4;
    const float4* src = (i < half_n) ? (const float4*)Wg : (const float4*)Wc;
    float4 v = src[(i < half_n) ? i : (i - half_n)];
    __half2 h0 = __floats2half2_rn(v.x, v.y);
    __half2 h1 = __floats2half2_rn(v.z, v.w);
    ((uint2*)g_Wh)[i] = make_uint2(*(uint32_t*)&h0, *(uint32_t*)&h1);
}

// ---------------------------------------------------------------------------
// Kernel 1: LayerNorm -> fp16 normed
// ---------------------------------------------------------------------------
__global__ void ln_kernel(const float* __restrict__ x,
                          const float* __restrict__ gamma,
                          const float* __restrict__ beta) {
    int row = blockIdx.x;
    int tid = threadIdx.x;      // 256
    const float4* xr = (const float4*)(x + (size_t)row * HH);
    float4 v = xr[tid];
    float s  = v.x + v.y + v.z + v.w;
    float s2 = v.x*v.x + v.y*v.y + v.z*v.z + v.w*v.w;
    #pragma unroll
    for (int o = 16; o > 0; o >>= 1) {
        s  += __shfl_xor_sync(0xFFFFFFFFu, s,  o);
        s2 += __shfl_xor_sync(0xFFFFFFFFu, s2, o);
    }
    __shared__ float ss[8], ss2[8];
    int w = tid >> 5, l = tid & 31;
    if (l == 0) { ss[w] = s; ss2[w] = s2; }
    __syncthreads();
    if (w == 0) {
        float a  = (l < 8) ? ss[l]  : 0.f;
        float a2 = (l < 8) ? ss2[l] : 0.f;
        #pragma unroll
        for (int o = 4; o > 0; o >>= 1) {
            a  += __shfl_xor_sync(0xFFFFFFFFu, a,  o);
            a2 += __shfl_xor_sync(0xFFFFFFFFu, a2, o);
        }
        if (l == 0) { ss[0] = a; ss2[0] = a2; }
    }
    __syncthreads();
    float mu  = ss[0] * (1.f / HH);
    float var = ss2[0] * (1.f / HH) - mu * mu;
    float rs  = rsqrtf(var + 1e-5f);
    float4 g  = ((const float4*)gamma)[tid];
    float4 bt = ((const float4*)beta)[tid];
    __half2 h0 = __floats2half2_rn((v.x - mu) * rs * g.x + bt.x,
                                   (v.y - mu) * rs * g.y + bt.y);
    __half2 h1 = __floats2half2_rn((v.z - mu) * rs * g.z + bt.z,
                                   (v.w - mu) * rs * g.w + bt.w);
    ((uint2*)g_normh)[(size_t)row * (HH/4) + tid] =
        make_uint2(*(uint32_t*)&h0, *(uint32_t*)&h1);
}

// ---------------------------------------------------------------------------
// Kernel 2: fp16 mma.sync (m16n8k16) GEMM, cp.async 3-stage pipeline,
// ldmatrix fragment loads. Block tile 128x128, BK=32, 8 warps, warp 64x32,
// 2 CTAs/SM. Logical N = 2048: bn<8 -> Wg+sigmoid -> g_z, bn>=8 -> Wc -> g_c.
// ---------------------------------------------------------------------------
#define BM 128
#define BN 128
#define BK 32                            // halves per K-tile
#define STAGES 3
#define SSTR_H 40                        // halves per smem row (80B: ldmatrix conflict-free)
#define A_STAGE_H (BM*SSTR_H)            // 5120 halves
#define B_STAGE_H (BN*SSTR_H)
#define GEMM_SMEM (STAGES*(A_STAGE_H+B_STAGE_H)*2)   // 61440 B

__global__ __launch_bounds__(256, 2) void gemm_kernel(
    const float* __restrict__ bg, const float* __restrict__ bc)
{
    extern __shared__ __half smh[];
    uint32_t sA_u = smem_u32(smh);
    uint32_t sB_u = sA_u + STAGES * A_STAGE_H * 2;

    int tid = threadIdx.x;               // 256
    int warp = tid >> 5, lane = tid & 31;
    int bn = blockIdx.x;                 // 0..15 (fast -> wave shares A in L2)
    int bm = blockIdx.y;                 // 0..127
    int wm = (warp & 1) * 64;            // 2 M-warps
    int wn = (warp >> 1) * 32;           // 4 N-warps

    bool isGate = (bn < 8);
    size_t woff = isGate ? 0 : (size_t)HH * HH;
    int nbase = (bn & 7) * BN;
    size_t arow = (size_t)bm * BM;

    const __half* Asrc0 = g_normh + arow * HH;
    const __half* Bsrc0 = g_Wh + woff + (size_t)nbase * HH;

    float acc[2][4][4];
    #pragma unroll
    for (int i = 0; i < 2; i++)
        #pragma unroll
        for (int j = 0; j < 4; j++)
            #pragma unroll
            for (int q = 0; q < 4; q++) acc[i][j][q] = 0.f;
    // NOTE: warp tile 64x32 -> 4 m16 subtiles x 4 n8 subtiles; acc[ii&1]... use [4][4]:
    float acc2[2][4][4];
    #pragma unroll
    for (int i = 0; i < 2; i++)
        #pragma unroll
        for (int j = 0; j < 4; j++)
            #pragma unroll
            for (int q = 0; q < 4; q++) acc2[i][j][q] = 0.f;

    // loads: per stage A 512 + B 512 16B-chunks, 256 thr -> 2+2 each
    int lr[2], lc[2];
    #pragma unroll
    for (int q = 0; q < 2; q++) {
        int f = tid + q * 256;
        lr[q] = f >> 2;                  // row 0..127
        lc[q] = (f & 3) * 8;             // half offset in row (16B chunks)
    }

    #define LOAD_STAGE(s, k0) do { \
        uint32_t abase = sA_u + (uint32_t)(s) * A_STAGE_H * 2; \
        uint32_t bbase = sB_u + (uint32_t)(s) * B_STAGE_H * 2; \
        _Pragma("unroll") \
        for (int q = 0; q < 2; q++) { \
            cp16(abase + (uint32_t)(lr[q] * SSTR_H + lc[q]) * 2, \
                 Asrc0 + (size_t)lr[q] * HH + (k0) + lc[q]); \
            cp16(bbase + (uint32_t)(lr[q] * SSTR_H + lc[q]) * 2, \
                 Bsrc0 + (size_t)lr[q] * HH + (k0) + lc[q]); \
        } \
    } while (0)

    LOAD_STAGE(0, 0);
    asm volatile("cp.async.commit_group;");
    LOAD_STAGE(1, BK);
    asm volatile("cp.async.commit_group;");

    // per-lane ldmatrix address components (bytes)
    uint32_t a_row = (uint32_t)(lane & 15);          // row within m16
    uint32_t a_kb  = ((lane >> 4) & 1) * 16;         // +8 halves
    uint32_t b_row = (uint32_t)((lane & 7) + ((lane >> 4) & 1) * 8);  // row within n16
    uint32_t b_kb  = ((lane >> 3) & 1) * 16;

    const int NK = HH / BK;              // 32
    for (int i = 0; i < NK; i++) {
        int s = i % STAGES;
        asm volatile("cp.async.wait_group 1;");
        __syncthreads();
        if (i + 2 < NK) {
            int s2 = (i + 2) % STAGES;
            LOAD_STAGE(s2, (i + 2) * BK);
        }
        asm volatile("cp.async.commit_group;");

        uint32_t abase = sA_u + (uint32_t)s * A_STAGE_H * 2;
        uint32_t bbase = sB_u + (uint32_t)s * B_STAGE_H * 2;

        #pragma unroll
        for (int ks = 0; ks < 2; ks++) {     // two k16 steps per K-tile
            unsigned af[4][4];
            #pragma unroll
            for (int ii = 0; ii < 4; ii++) {
                uint32_t addr = abase + (wm + ii * 16 + a_row) * (SSTR_H * 2)
                                + ks * 32 + a_kb;
                asm volatile(
                    "ldmatrix.sync.aligned.m8n8.x4.shared.b16 {%0,%1,%2,%3}, [%4];"
                    : "=r"(af[ii][0]), "=r"(af[ii][1]), "=r"(af[ii][2]), "=r"(af[ii][3])
                    : "r"(addr));
            }
            unsigned bf[4][2];
            #pragma unroll
            for (int j2 = 0; j2 < 2; j2++) {  // each x4 covers two n8 subtiles
                uint32_t addr = bbase + (wn + j2 * 16 + b_row) * (SSTR_H * 2)
                                + ks * 32 + b_kb;
                asm volatile(
                    "ldmatrix.sync.aligned.m8n8.x4.shared.b16 {%0,%1,%2,%3}, [%4];"
                    : "=r"(bf[j2*2][0]), "=r"(bf[j2*2][1]),
                      "=r"(bf[j2*2+1][0]), "=r"(bf[j2*2+1][1])
                    : "r"(addr));
            }
            #pragma unroll
            for (int ii = 0; ii < 4; ii++) {
                float* ac = (ii < 2) ? acc[ii] [0] : acc2[ii-2][0];
                #pragma unroll
                for (int j = 0; j < 4; j++) {
                    float* a4 = ac + j * 4;
                    asm volatile(
                        "mma.sync.aligned.m16n8k16.row.col.f32.f16.f16.f32 "
                        "{%0,%1,%2,%3},{%4,%5,%6,%7},{%8,%9},{%0,%1,%2,%3};"
                        : "+f"(a4[0]), "+f"(a4[1]), "+f"(a4[2]), "+f"(a4[3])
                        : "r"(af[ii][0]), "r"(af[ii][1]), "r"(af[ii][2]), "r"(af[ii][3]),
                          "r"(bf[j][0]), "r"(bf[j][1]));
                }
            }
        }
    }
    asm volatile("cp.async.wait_group 0;");

    // Epilogue: +bias, optional sigmoid, write z or c
    int r  = lane >> 2;
    int cq = (lane & 3) * 2;
    const float* bias = isGate ? bg : bc;
    float* outp = isGate ? g_z : g_c;
    #pragma unroll
    for (int ii = 0; ii < 4; ii++) {
        float* ac = (ii < 2) ? acc[ii][0] : acc2[ii-2][0];
        #pragma unroll
        for (int j = 0; j < 4; j++) {
            float* a4 = ac + j * 4;
            int m0 = bm * BM + wm + ii * 16 + r;
            int n0 = nbase + wn + j * 8 + cq;
            float b0 = bias[n0], b1 = bias[n0 + 1];
            float v0 = a4[0] + b0;
            float v1 = a4[1] + b1;
            float v2 = a4[2] + b0;
            float v3 = a4[3] + b1;
            if (isGate) {
                v0 = 1.f / (1.f + __expf(-v0));
                v1 = 1.f / (1.f + __expf(-v1));
                v2 = 1.f / (1.f + __expf(-v2));
                v3 = 1.f / (1.f + __expf(-v3));
            }
            *(float2*)(outp + (size_t)m0 * HH + n0)       = make_float2(v0, v1);
            *(float2*)(outp + (size_t)(m0 + 8) * HH + n0) = make_float2(v2, v3);
        }
    }
}

// ---------------------------------------------------------------------------
// Scan phase A: per-(b, chunk, hid) aggregates (P = prod(1-z), S = scan from 0)
// ---------------------------------------------------------------------------
__global__ void scanA_kernel() {
    int g   = blockIdx.x * blockDim.x + threadIdx.x;   // BB*NCHUNK*HH threads
    int hid = g % HH;
    int ck  = (g / HH) % NCHUNK;
    int b   = g / (HH * NCHUNK);
    size_t base = ((size_t)(b * TT + ck * CHUNK)) * HH + hid;
    float P = 1.f, S = 0.f;
    #pragma unroll 8
    for (int t = 0; t < CHUNK; t++) {
        float z = g_z[base + (size_t)t * HH];
        float c = g_c[base + (size_t)t * HH];
        float a = 1.f - z;
        S = a * S + z * c;
        P = a * P;
    }
    g_P[g] = P;
    g_S[g] = S;
}

// ---------------------------------------------------------------------------
// Scan phase B: parallel Kogge-Stone over 64 chunk aggregates per (b,hid).
// ---------------------------------------------------------------------------
__global__ void scanB_kernel() {
    int gt   = blockIdx.x * blockDim.x + threadIdx.x;
    int lane = gt & 31;
    int wg   = gt >> 5;                 // 0..BB*HH-1
    int hid  = wg & (HH - 1);
    int b    = wg >> 10;                // HH = 1024
    int k0   = 2 * lane;
    size_t i0 = ((size_t)(b * NCHUNK + k0)) * HH + hid;
    float P0 = g_P[i0],      S0 = g_S[i0];
    float P1 = g_P[i0 + HH], S1 = g_S[i0 + HH];
    float cP = P1 * P0;
    float cS = P1 * S0 + S1;
    #pragma unroll
    for (int d = 1; d < 32; d <<= 1) {
        float pP = __shfl_up_sync(0xFFFFFFFFu, cP, d);
        float pS = __shfl_up_sync(0xFFFFFFFFu, cS, d);
        if (lane >= d) { cS = cP * pS + cS; cP = cP * pP; }
    }
    float eS = __shfl_up_sync(0xFFFFFFFFu, cS, 1);
    if (lane == 0) eS = 0.f;
    g_hin[i0]      = eS;
    g_hin[i0 + HH] = P0 * eS + S0;
}

// ---------------------------------------------------------------------------
// Scan phase C: re-run each chunk with the correct h_in, fuse residual +x
// ---------------------------------------------------------------------------
__global__ void scanC_kernel(const float* __restrict__ x, float* __restrict__ out) {
    int g   = blockIdx.x * blockDim.x + threadIdx.x;
    int hid = g % HH;
    int ck  = (g / HH) % NCHUNK;
    int b   = g / (HH * NCHUNK);
    size_t base = ((size_t)(b * TT + ck * CHUNK)) * HH + hid;
    float h = g_hin[g];
    #pragma unroll 8
    for (int t = 0; t < CHUNK; t++) {
        size_t idx = base + (size_t)t * HH;
        float z = g_z[idx];
        float c = g_c[idx];
        h = (1.f - z) * h + z * c;
        out[idx] = h + x[idx];
    }
}

// ---------------------------------------------------------------------------
extern "C" void kernel_launch(void* const* d_in, const int* in_sizes, int n_in,
                              void* d_out, int out_size) {
    const float* x     = (const float*)d_in[0];
    const float* gamma = (const float*)d_in[1];
    const float* beta  = (const float*)d_in[2];
    const float* Wg    = (const float*)d_in[3];
    const float* bg    = (const float*)d_in[4];
    const float* Wc    = (const float*)d_in[5];
    const float* bc    = (const float*)d_in[6];
    float* out = (float*)d_out;

    halfW_kernel<<<(2 * HH * HH / 4) / 256, 256>>>(Wg, Wc);
    ln_kernel<<<M_TOTAL, 256>>>(x, gamma, beta);

    cudaFuncSetAttribute(gemm_kernel,
                         cudaFuncAttributeMaxDynamicSharedMemorySize, GEMM_SMEM);
    dim3 ggrid(2 * HH / BN, M_TOTAL / BM);   // (16, 128)
    gemm_kernel<<<ggrid, 256, GEMM_SMEM>>>(bg, bc);

    scanA_kernel<<<(BB * NCHUNK * HH) / 256, 256>>>();
    scanB_kernel<<<(BB * HH * 32) / 256, 256>>>();
    scanC_kernel<<<(BB * NCHUNK * HH) / 256, 256>>>(x, out);
}

// round 8
// speedup vs baseline: 1.7841x; 1.0649x over previous
#include <cuda_runtime.h>
#include <cuda_fp16.h>
#include <cstdint>
#include <math.h>

// Problem dims (fixed by reference setup_inputs)
#define BB 4
#define TT 4096
#define HH 1024
#define M_TOTAL (BB*TT)      // 16384
#define NCHUNK 64
#define CHUNK (TT/NCHUNK)    // 64

// Scratch (allocation-free rule: __device__ globals)
__device__ __half g_normh[(size_t)M_TOTAL*HH];   // fp16 LN output (32MB)
__device__ __half g_Wh[(size_t)2*HH*HH];         // fp16 [Wg; Wc] (4MB)
__device__ __half g_zh[(size_t)M_TOTAL*HH];      // fp16 gate (32MB)
__device__ __half g_ch[(size_t)M_TOTAL*HH];      // fp16 candidate (32MB)
__device__ float g_P[BB*NCHUNK*HH];
__device__ float g_S[BB*NCHUNK*HH];
__device__ float g_hin[BB*NCHUNK*HH];

__device__ __forceinline__ uint32_t smem_u32(const void* p) {
    uint32_t a;
    asm("{ .reg .u64 t; cvta.to.shared.u64 t, %1; cvt.u32.u64 %0, t; }" : "=r"(a) : "l"(p));
    return a;
}
__device__ __forceinline__ void cp16(uint32_t dst, const void* src) {
    asm volatile("cp.async.cg.shared.global [%0], [%1], 16;" :: "r"(dst), "l"(src));
}

// ---------------------------------------------------------------------------
// Kernel 0: convert Wg/Wc to fp16 into g_Wh
// ---------------------------------------------------------------------------
__global__ void halfW_kernel(const float* __restrict__ Wg,
                             const float* __restrict__ Wc) {
    int i = blockIdx.x * blockDim.x + threadIdx.x;   // over 2*HH*HH/4
    int half_n = HH * HH / 4;
    const float4* src = (i < half_n) ? (const float4*)Wg : (const float4*)Wc;
    float4 v = src[(i < half_n) ? i : (i - half_n)];
    __half2 h0 = __floats2half2_rn(v.x, v.y);
    __half2 h1 = __floats2half2_rn(v.z, v.w);
    ((uint2*)g_Wh)[i] = make_uint2(*(uint32_t*)&h0, *(uint32_t*)&h1);
}

// ---------------------------------------------------------------------------
// Kernel 1: LayerNorm -> fp16 normed
// ---------------------------------------------------------------------------
__global__ void ln_kernel(const float* __restrict__ x,
                          const float* __restrict__ gamma,
                          const float* __restrict__ beta) {
    int row = blockIdx.x;
    int tid = threadIdx.x;      // 256
    const float4* xr = (const float4*)(x + (size_t)row * HH);
    float4 v = xr[tid];
    float s  = v.x + v.y + v.z + v.w;
    float s2 = v.x*v.x + v.y*v.y + v.z*v.z + v.w*v.w;
    #pragma unroll
    for (int o = 16; o > 0; o >>= 1) {
        s  += __shfl_xor_sync(0xFFFFFFFFu, s,  o);
        s2 += __shfl_xor_sync(0xFFFFFFFFu, s2, o);
    }
    __shared__ float ss[8], ss2[8];
    int w = tid >> 5, l = tid & 31;
    if (l == 0) { ss[w] = s; ss2[w] = s2; }
    __syncthreads();
    if (w == 0) {
        float a  = (l < 8) ? ss[l]  : 0.f;
        float a2 = (l < 8) ? ss2[l] : 0.f;
        #pragma unroll
        for (int o = 4; o > 0; o >>= 1) {
            a  += __shfl_xor_sync(0xFFFFFFFFu, a,  o);
            a2 += __shfl_xor_sync(0xFFFFFFFFu, a2, o);
        }
        if (l == 0) { ss[0] = a; ss2[0] = a2; }
    }
    __syncthreads();
    float mu  = ss[0] * (1.f / HH);
    float var = ss2[0] * (1.f / HH) - mu * mu;
    float rs  = rsqrtf(var + 1e-5f);
    float4 g  = ((const float4*)gamma)[tid];
    float4 bt = ((const float4*)beta)[tid];
    __half2 h0 = __floats2half2_rn((v.x - mu) * rs * g.x + bt.x,
                                   (v.y - mu) * rs * g.y + bt.y);
    __half2 h1 = __floats2half2_rn((v.z - mu) * rs * g.z + bt.z,
                                   (v.w - mu) * rs * g.w + bt.w);
    ((uint2*)g_normh)[(size_t)row * (HH/4) + tid] =
        make_uint2(*(uint32_t*)&h0, *(uint32_t*)&h1);
}

// ---------------------------------------------------------------------------
// Kernel 2: fp16 mma.sync (m16n8k16) GEMM, cp.async 4-stage pipeline,
// ldmatrix fragment loads. Block tile 128x128, BK=32, 4 warps (128 thr),
// warp tile 64x64 (2x2 warp grid) -> A,B each re-read only 2x from smem.
// 2 CTAs/SM. Logical N = 2048: bn<8 -> Wg+sigmoid -> g_zh, bn>=8 -> g_ch.
// ---------------------------------------------------------------------------
#define BM 128
#define BN 128
#define BK 32                            // halves per K-tile
#define STAGES 4
#define SSTR_H 40                        // halves per smem row (80B: ldmatrix conflict-free)
#define A_STAGE_H (BM*SSTR_H)            // 5120 halves
#define B_STAGE_H (BN*SSTR_H)
#define GEMM_SMEM (STAGES*(A_STAGE_H+B_STAGE_H)*2)   // 81920 B

__global__ __launch_bounds__(128, 2) void gemm_kernel(
    const float* __restrict__ bg, const float* __restrict__ bc)
{
    extern __shared__ __half smh[];
    uint32_t sA_u = smem_u32(smh);
    uint32_t sB_u = sA_u + STAGES * A_STAGE_H * 2;

    int tid = threadIdx.x;               // 128
    int warp = tid >> 5, lane = tid & 31;
    int bn = blockIdx.x;                 // 0..15 (fast -> wave shares A in L2)
    int bm = blockIdx.y;                 // 0..127
    int wm = (warp & 1) * 64;            // 2 M-warps
    int wn = (warp >> 1) * 64;           // 2 N-warps

    bool isGate = (bn < 8);
    size_t woff = isGate ? 0 : (size_t)HH * HH;
    int nbase = (bn & 7) * BN;
    size_t arow = (size_t)bm * BM;

    const __half* Asrc0 = g_normh + arow * HH;
    const __half* Bsrc0 = g_Wh + woff + (size_t)nbase * HH;

    float acc[4][8][4];                  // 4 m16 x 8 n8 x 4 regs
    #pragma unroll
    for (int i = 0; i < 4; i++)
        #pragma unroll
        for (int j = 0; j < 8; j++)
            #pragma unroll
            for (int q = 0; q < 4; q++) acc[i][j][q] = 0.f;

    // loads: per stage A 512 + B 512 16B-chunks, 128 thr -> 4+4 each
    int lr[4], lc[4];
    #pragma unroll
    for (int q = 0; q < 4; q++) {
        int f = tid + q * 128;
        lr[q] = f >> 2;                  // row 0..127
        lc[q] = (f & 3) * 8;             // half offset in row (16B chunks)
    }

    #define LOAD_STAGE(s, k0) do { \
        uint32_t abase = sA_u + (uint32_t)(s) * A_STAGE_H * 2; \
        uint32_t bbase = sB_u + (uint32_t)(s) * B_STAGE_H * 2; \
        _Pragma("unroll") \
        for (int q = 0; q < 4; q++) { \
            cp16(abase + (uint32_t)(lr[q] * SSTR_H + lc[q]) * 2, \
                 Asrc0 + (size_t)lr[q] * HH + (k0) + lc[q]); \
            cp16(bbase + (uint32_t)(lr[q] * SSTR_H + lc[q]) * 2, \
                 Bsrc0 + (size_t)lr[q] * HH + (k0) + lc[q]); \
        } \
    } while (0)

    LOAD_STAGE(0, 0);
    asm volatile("cp.async.commit_group;");
    LOAD_STAGE(1, BK);
    asm volatile("cp.async.commit_group;");
    LOAD_STAGE(2, 2 * BK);
    asm volatile("cp.async.commit_group;");

    // per-lane ldmatrix address components (bytes)
    uint32_t a_row = (uint32_t)(lane & 15);          // row within m16
    uint32_t a_kb  = ((lane >> 4) & 1) * 16;         // +8 halves
    uint32_t b_row = (uint32_t)((lane & 7) + ((lane >> 4) & 1) * 8);  // row within n16
    uint32_t b_kb  = ((lane >> 3) & 1) * 16;

    const int NK = HH / BK;              // 32
    for (int i = 0; i < NK; i++) {
        int s = i & (STAGES - 1);
        asm volatile("cp.async.wait_group 2;");
        __syncthreads();
        if (i + 3 < NK) {
            int s2 = (i + 3) & (STAGES - 1);
            LOAD_STAGE(s2, (i + 3) * BK);
        }
        asm volatile("cp.async.commit_group;");

        uint32_t abase = sA_u + (uint32_t)s * A_STAGE_H * 2;
        uint32_t bbase = sB_u + (uint32_t)s * B_STAGE_H * 2;

        #pragma unroll
        for (int ks = 0; ks < 2; ks++) {     // two k16 steps per K-tile
            unsigned af[4][4];
            #pragma unroll
            for (int ii = 0; ii < 4; ii++) {
                uint32_t addr = abase + (wm + ii * 16 + a_row) * (SSTR_H * 2)
                                + ks * 32 + a_kb;
                asm volatile(
                    "ldmatrix.sync.aligned.m8n8.x4.shared.b16 {%0,%1,%2,%3}, [%4];"
                    : "=r"(af[ii][0]), "=r"(af[ii][1]), "=r"(af[ii][2]), "=r"(af[ii][3])
                    : "r"(addr));
            }
            unsigned bf[8][2];
            #pragma unroll
            for (int j2 = 0; j2 < 4; j2++) {  // each x4 covers two n8 subtiles
                uint32_t addr = bbase + (wn + j2 * 16 + b_row) * (SSTR_H * 2)
                                + ks * 32 + b_kb;
                asm volatile(
                    "ldmatrix.sync.aligned.m8n8.x4.shared.b16 {%0,%1,%2,%3}, [%4];"
                    : "=r"(bf[j2*2][0]), "=r"(bf[j2*2][1]),
                      "=r"(bf[j2*2+1][0]), "=r"(bf[j2*2+1][1])
                    : "r"(addr));
            }
            #pragma unroll
            for (int ii = 0; ii < 4; ii++) {
                #pragma unroll
                for (int j = 0; j < 8; j++) {
                    float* a4 = acc[ii][j];
                    asm volatile(
                        "mma.sync.aligned.m16n8k16.row.col.f32.f16.f16.f32 "
                        "{%0,%1,%2,%3},{%4,%5,%6,%7},{%8,%9},{%0,%1,%2,%3};"
                        : "+f"(a4[0]), "+f"(a4[1]), "+f"(a4[2]), "+f"(a4[3])
                        : "r"(af[ii][0]), "r"(af[ii][1]), "r"(af[ii][2]), "r"(af[ii][3]),
                          "r"(bf[j][0]), "r"(bf[j][1]));
                }
            }
        }
    }
    asm volatile("cp.async.wait_group 0;");

    // Epilogue: +bias, optional sigmoid, write z or c as fp16
    int r  = lane >> 2;
    int cq = (lane & 3) * 2;
    const float* bias = isGate ? bg : bc;
    __half* outp = isGate ? g_zh : g_ch;
    #pragma unroll
    for (int ii = 0; ii < 4; ii++) {
        #pragma unroll
        for (int j = 0; j < 8; j++) {
            float* a4 = acc[ii][j];
            int m0 = bm * BM + wm + ii * 16 + r;
            int n0 = nbase + wn + j * 8 + cq;
            float b0 = bias[n0], b1 = bias[n0 + 1];
            float v0 = a4[0] + b0;
            float v1 = a4[1] + b1;
            float v2 = a4[2] + b0;
            float v3 = a4[3] + b1;
            if (isGate) {
                v0 = 1.f / (1.f + __expf(-v0));
                v1 = 1.f / (1.f + __expf(-v1));
                v2 = 1.f / (1.f + __expf(-v2));
                v3 = 1.f / (1.f + __expf(-v3));
            }
            *(__half2*)(outp + (size_t)m0 * HH + n0)       = __floats2half2_rn(v0, v1);
            *(__half2*)(outp + (size_t)(m0 + 8) * HH + n0) = __floats2half2_rn(v2, v3);
        }
    }
}

// ---------------------------------------------------------------------------
// Scan phase A: per-(b, chunk, hid) aggregates (P = prod(1-z), S = scan from 0)
// ---------------------------------------------------------------------------
__global__ void scanA_kernel() {
    int g   = blockIdx.x * blockDim.x + threadIdx.x;   // BB*NCHUNK*HH threads
    int hid = g % HH;
    int ck  = (g / HH) % NCHUNK;
    int b   = g / (HH * NCHUNK);
    size_t base = ((size_t)(b * TT + ck * CHUNK)) * HH + hid;
    float P = 1.f, S = 0.f;
    #pragma unroll 8
    for (int t = 0; t < CHUNK; t++) {
        size_t idx = base + (size_t)t * HH;
        float z = __half2float(g_zh[idx]);
        float c = __half2float(g_ch[idx]);
        float a = 1.f - z;
        S = a * S + z * c;
        P = a * P;
    }
    g_P[g] = P;
    g_S[g] = S;
}

// ---------------------------------------------------------------------------
// Scan phase B: parallel Kogge-Stone over 64 chunk aggregates per (b,hid).
// ---------------------------------------------------------------------------
__global__ void scanB_kernel() {
    int gt   = blockIdx.x * blockDim.x + threadIdx.x;
    int lane = gt & 31;
    int wg   = gt >> 5;                 // 0..BB*HH-1
    int hid  = wg & (HH - 1);
    int b    = wg >> 10;                // HH = 1024
    int k0   = 2 * lane;
    size_t i0 = ((size_t)(b * NCHUNK + k0)) * HH + hid;
    float P0 = g_P[i0],      S0 = g_S[i0];
    float P1 = g_P[i0 + HH], S1 = g_S[i0 + HH];
    float cP = P1 * P0;
    float cS = P1 * S0 + S1;
    #pragma unroll
    for (int d = 1; d < 32; d <<= 1) {
        float pP = __shfl_up_sync(0xFFFFFFFFu, cP, d);
        float pS = __shfl_up_sync(0xFFFFFFFFu, cS, d);
        if (lane >= d) { cS = cP * pS + cS; cP = cP * pP; }
    }
    float eS = __shfl_up_sync(0xFFFFFFFFu, cS, 1);
    if (lane == 0) eS = 0.f;
    g_hin[i0]      = eS;
    g_hin[i0 + HH] = P0 * eS + S0;
}

// ---------------------------------------------------------------------------
// Scan phase C: re-run each chunk with the correct h_in, fuse residual +x
// ---------------------------------------------------------------------------
__global__ void scanC_kernel(const float* __restrict__ x, float* __restrict__ out) {
    int g   = blockIdx.x * blockDim.x + threadIdx.x;
    int hid = g % HH;
    int ck  = (g / HH) % NCHUNK;
    int b   = g / (HH * NCHUNK);
    size_t base = ((size_t)(b * TT + ck * CHUNK)) * HH + hid;
    float h = g_hin[g];
    #pragma unroll 8
    for (int t = 0; t < CHUNK; t++) {
        size_t idx = base + (size_t)t * HH;
        float z = __half2float(g_zh[idx]);
        float c = __half2float(g_ch[idx]);
        h = (1.f - z) * h + z * c;
        out[idx] = h + x[idx];
    }
}

// ---------------------------------------------------------------------------
extern "C" void kernel_launch(void* const* d_in, const int* in_sizes, int n_in,
                              void* d_out, int out_size) {
    const float* x     = (const float*)d_in[0];
    const float* gamma = (const float*)d_in[1];
    const float* beta  = (const float*)d_in[2];
    const float* Wg    = (const float*)d_in[3];
    const float* bg    = (const float*)d_in[4];
    const float* Wc    = (const float*)d_in[5];
    const float* bc    = (const float*)d_in[6];
    float* out = (float*)d_out;

    halfW_kernel<<<(2 * HH * HH / 4) / 256, 256>>>(Wg, Wc);
    ln_kernel<<<M_TOTAL, 256>>>(x, gamma, beta);

    cudaFuncSetAttribute(gemm_kernel,
                         cudaFuncAttributeMaxDynamicSharedMemorySize, GEMM_SMEM);
    dim3 ggrid(2 * HH / BN, M_TOTAL / BM);   // (16, 128)
    gemm_kernel<<<ggrid, 128, GEMM_SMEM>>>(bg, bc);

    scanA_kernel<<<(BB * NCHUNK * HH) / 256, 256>>>();
    scanB_kernel<<<(BB * HH * 32) / 256, 256>>>();
    scanC_kernel<<<(BB * NCHUNK * HH) / 256, 256>>>(x, out);
}

// round 9
// speedup vs baseline: 1.8825x; 1.0552x over previous
#include <cuda_runtime.h>
#include <cuda_fp16.h>
#include <cstdint>
#include <math.h>

// Problem dims (fixed by reference setup_inputs)
#define BB 4
#define TT 4096
#define HH 1024
#define M_TOTAL (BB*TT)      // 16384
#define NCHUNK 64
#define CHUNK (TT/NCHUNK)    // 64

// Scratch (allocation-free rule: __device__ globals)
__device__ __half g_normh[(size_t)M_TOTAL*HH];   // fp16 LN output (32MB)
__device__ __half g_Wh[(size_t)2*HH*HH];         // fp16 [Wg; Wc] (4MB)
__device__ __half g_zh[(size_t)M_TOTAL*HH];      // fp16 gate (32MB)
__device__ __half g_ch[(size_t)M_TOTAL*HH];      // fp16 candidate (32MB)
__device__ float g_P[BB*NCHUNK*HH];
__device__ float g_S[BB*NCHUNK*HH];
__device__ float g_hin[BB*NCHUNK*HH];

__device__ __forceinline__ uint32_t smem_u32(const void* p) {
    uint32_t a;
    asm("{ .reg .u64 t; cvta.to.shared.u64 t, %1; cvt.u32.u64 %0, t; }" : "=r"(a) : "l"(p));
    return a;
}
__device__ __forceinline__ void cp16(uint32_t dst, const void* src) {
    asm volatile("cp.async.cg.shared.global [%0], [%1], 16;" :: "r"(dst), "l"(src));
}

// ---------------------------------------------------------------------------
// Kernel 0: convert Wg/Wc to fp16 into g_Wh
// ---------------------------------------------------------------------------
__global__ void halfW_kernel(const float* __restrict__ Wg,
                             const float* __restrict__ Wc) {
    int i = blockIdx.x * blockDim.x + threadIdx.x;   // over 2*HH*HH/4
    int half_n = HH * HH / 4;
    const float4* src = (i < half_n) ? (const float4*)Wg : (const float4*)Wc;
    float4 v = src[(i < half_n) ? i : (i - half_n)];
    __half2 h0 = __floats2half2_rn(v.x, v.y);
    __half2 h1 = __floats2half2_rn(v.z, v.w);
    ((uint2*)g_Wh)[i] = make_uint2(*(uint32_t*)&h0, *(uint32_t*)&h1);
}

// ---------------------------------------------------------------------------
// Kernel 1: LayerNorm -> fp16 normed. Warp-per-row (8 rows/block), pure
// shfl reduction, 8 float4/lane in flight, no block barrier.
// ---------------------------------------------------------------------------
__global__ __launch_bounds__(256) void ln_kernel(
    const float* __restrict__ x,
    const float* __restrict__ gamma,
    const float* __restrict__ beta) {
    int warp = threadIdx.x >> 5, lane = threadIdx.x & 31;
    int row = blockIdx.x * 8 + warp;
    const float4* xr = (const float4*)(x + (size_t)row * HH);

    float4 v[8];
    float s = 0.f, s2 = 0.f;
    #pragma unroll
    for (int q = 0; q < 8; q++) {
        v[q] = xr[lane + 32 * q];
        s  += v[q].x + v[q].y + v[q].z + v[q].w;
        s2 += v[q].x*v[q].x + v[q].y*v[q].y + v[q].z*v[q].z + v[q].w*v[q].w;
    }
    #pragma unroll
    for (int o = 16; o > 0; o >>= 1) {
        s  += __shfl_xor_sync(0xFFFFFFFFu, s,  o);
        s2 += __shfl_xor_sync(0xFFFFFFFFu, s2, o);
    }
    float mu  = s * (1.f / HH);
    float var = s2 * (1.f / HH) - mu * mu;
    float rs  = rsqrtf(var + 1e-5f);

    uint2* orow = (uint2*)g_normh + (size_t)row * (HH / 4);
    #pragma unroll
    for (int q = 0; q < 8; q++) {
        int f = lane + 32 * q;
        float4 g  = ((const float4*)gamma)[f];
        float4 bt = ((const float4*)beta)[f];
        __half2 h0 = __floats2half2_rn((v[q].x - mu) * rs * g.x + bt.x,
                                       (v[q].y - mu) * rs * g.y + bt.y);
        __half2 h1 = __floats2half2_rn((v[q].z - mu) * rs * g.z + bt.z,
                                       (v[q].w - mu) * rs * g.w + bt.w);
        orow[f] = make_uint2(*(uint32_t*)&h0, *(uint32_t*)&h1);
    }
}

// ---------------------------------------------------------------------------
// Kernel 2: fp16 mma.sync (m16n8k16) GEMM, cp.async 4-stage pipeline,
// ldmatrix fragment loads. Block tile 128x128, BK=32, 4 warps (128 thr),
// warp tile 64x64 (2x2 warp grid). 2 CTAs/SM. At the mma.sync HMMA ceiling.
// Logical N = 2048: bn<8 -> Wg+sigmoid -> g_zh, bn>=8 -> g_ch.
// ---------------------------------------------------------------------------
#define BM 128
#define BN 128
#define BK 32                            // halves per K-tile
#define STAGES 4
#define SSTR_H 40                        // halves per smem row (80B: ldmatrix conflict-free)
#define A_STAGE_H (BM*SSTR_H)            // 5120 halves
#define B_STAGE_H (BN*SSTR_H)
#define GEMM_SMEM (STAGES*(A_STAGE_H+B_STAGE_H)*2)   // 81920 B

__global__ __launch_bounds__(128, 2) void gemm_kernel(
    const float* __restrict__ bg, const float* __restrict__ bc)
{
    extern __shared__ __half smh[];
    uint32_t sA_u = smem_u32(smh);
    uint32_t sB_u = sA_u + STAGES * A_STAGE_H * 2;

    int tid = threadIdx.x;               // 128
    int warp = tid >> 5, lane = tid & 31;
    int bn = blockIdx.x;                 // 0..15 (fast -> wave shares A in L2)
    int bm = blockIdx.y;                 // 0..127
    int wm = (warp & 1) * 64;            // 2 M-warps
    int wn = (warp >> 1) * 64;           // 2 N-warps

    bool isGate = (bn < 8);
    size_t woff = isGate ? 0 : (size_t)HH * HH;
    int nbase = (bn & 7) * BN;
    size_t arow = (size_t)bm * BM;

    const __half* Asrc0 = g_normh + arow * HH;
    const __half* Bsrc0 = g_Wh + woff + (size_t)nbase * HH;

    float acc[4][8][4];                  // 4 m16 x 8 n8 x 4 regs
    #pragma unroll
    for (int i = 0; i < 4; i++)
        #pragma unroll
        for (int j = 0; j < 8; j++)
            #pragma unroll
            for (int q = 0; q < 4; q++) acc[i][j][q] = 0.f;

    // loads: per stage A 512 + B 512 16B-chunks, 128 thr -> 4+4 each
    int lr[4], lc[4];
    #pragma unroll
    for (int q = 0; q < 4; q++) {
        int f = tid + q * 128;
        lr[q] = f >> 2;                  // row 0..127
        lc[q] = (f & 3) * 8;             // half offset in row (16B chunks)
    }

    #define LOAD_STAGE(s, k0) do { \
        uint32_t abase = sA_u + (uint32_t)(s) * A_STAGE_H * 2; \
        uint32_t bbase = sB_u + (uint32_t)(s) * B_STAGE_H * 2; \
        _Pragma("unroll") \
        for (int q = 0; q < 4; q++) { \
            cp16(abase + (uint32_t)(lr[q] * SSTR_H + lc[q]) * 2, \
                 Asrc0 + (size_t)lr[q] * HH + (k0) + lc[q]); \
            cp16(bbase + (uint32_t)(lr[q] * SSTR_H + lc[q]) * 2, \
                 Bsrc0 + (size_t)lr[q] * HH + (k0) + lc[q]); \
        } \
    } while (0)

    LOAD_STAGE(0, 0);
    asm volatile("cp.async.commit_group;");
    LOAD_STAGE(1, BK);
    asm volatile("cp.async.commit_group;");
    LOAD_STAGE(2, 2 * BK);
    asm volatile("cp.async.commit_group;");

    // per-lane ldmatrix address components (bytes)
    uint32_t a_row = (uint32_t)(lane & 15);          // row within m16
    uint32_t a_kb  = ((lane >> 4) & 1) * 16;         // +8 halves
    uint32_t b_row = (uint32_t)((lane & 7) + ((lane >> 4) & 1) * 8);  // row within n16
    uint32_t b_kb  = ((lane >> 3) & 1) * 16;

    const int NK = HH / BK;              // 32
    for (int i = 0; i < NK; i++) {
        int s = i & (STAGES - 1);
        asm volatile("cp.async.wait_group 2;");
        __syncthreads();
        if (i + 3 < NK) {
            int s2 = (i + 3) & (STAGES - 1);
            LOAD_STAGE(s2, (i + 3) * BK);
        }
        asm volatile("cp.async.commit_group;");

        uint32_t abase = sA_u + (uint32_t)s * A_STAGE_H * 2;
        uint32_t bbase = sB_u + (uint32_t)s * B_STAGE_H * 2;

        #pragma unroll
        for (int ks = 0; ks < 2; ks++) {     // two k16 steps per K-tile
            unsigned af[4][4];
            #pragma unroll
            for (int ii = 0; ii < 4; ii++) {
                uint32_t addr = abase + (wm + ii * 16 + a_row) * (SSTR_H * 2)
                                + ks * 32 + a_kb;
                asm volatile(
                    "ldmatrix.sync.aligned.m8n8.x4.shared.b16 {%0,%1,%2,%3}, [%4];"
                    : "=r"(af[ii][0]), "=r"(af[ii][1]), "=r"(af[ii][2]), "=r"(af[ii][3])
                    : "r"(addr));
            }
            unsigned bf[8][2];
            #pragma unroll
            for (int j2 = 0; j2 < 4; j2++) {  // each x4 covers two n8 subtiles
                uint32_t addr = bbase + (wn + j2 * 16 + b_row) * (SSTR_H * 2)
                                + ks * 32 + b_kb;
                asm volatile(
                    "ldmatrix.sync.aligned.m8n8.x4.shared.b16 {%0,%1,%2,%3}, [%4];"
                    : "=r"(bf[j2*2][0]), "=r"(bf[j2*2][1]),
                      "=r"(bf[j2*2+1][0]), "=r"(bf[j2*2+1][1])
                    : "r"(addr));
            }
            #pragma unroll
            for (int ii = 0; ii < 4; ii++) {
                #pragma unroll
                for (int j = 0; j < 8; j++) {
                    float* a4 = acc[ii][j];
                    asm volatile(
                        "mma.sync.aligned.m16n8k16.row.col.f32.f16.f16.f32 "
                        "{%0,%1,%2,%3},{%4,%5,%6,%7},{%8,%9},{%0,%1,%2,%3};"
                        : "+f"(a4[0]), "+f"(a4[1]), "+f"(a4[2]), "+f"(a4[3])
                        : "r"(af[ii][0]), "r"(af[ii][1]), "r"(af[ii][2]), "r"(af[ii][3]),
                          "r"(bf[j][0]), "r"(bf[j][1]));
                }
            }
        }
    }
    asm volatile("cp.async.wait_group 0;");

    // Epilogue: +bias, optional sigmoid, write z or c as fp16
    int r  = lane >> 2;
    int cq = (lane & 3) * 2;
    const float* bias = isGate ? bg : bc;
    __half* outp = isGate ? g_zh : g_ch;
    #pragma unroll
    for (int ii = 0; ii < 4; ii++) {
        #pragma unroll
        for (int j = 0; j < 8; j++) {
            float* a4 = acc[ii][j];
            int m0 = bm * BM + wm + ii * 16 + r;
            int n0 = nbase + wn + j * 8 + cq;
            float b0 = bias[n0], b1 = bias[n0 + 1];
            float v0 = a4[0] + b0;
            float v1 = a4[1] + b1;
            float v2 = a4[2] + b0;
            float v3 = a4[3] + b1;
            if (isGate) {
                v0 = 1.f / (1.f + __expf(-v0));
                v1 = 1.f / (1.f + __expf(-v1));
                v2 = 1.f / (1.f + __expf(-v2));
                v3 = 1.f / (1.f + __expf(-v3));
            }
            *(__half2*)(outp + (size_t)m0 * HH + n0)       = __floats2half2_rn(v0, v1);
            *(__half2*)(outp + (size_t)(m0 + 8) * HH + n0) = __floats2half2_rn(v2, v3);
        }
    }
}

// ---------------------------------------------------------------------------
// Scan phase A: per-(b, chunk, hid) aggregates. 2 hids/thread via half2
// (4B loads, float2 state, float2 stores) -> 2x bytes in flight per thread.
// ---------------------------------------------------------------------------
__global__ void scanA_kernel() {
    int g2  = blockIdx.x * blockDim.x + threadIdx.x;   // over BB*NCHUNK*HH/2
    int hp  = g2 % (HH / 2);
    int ck  = (g2 / (HH / 2)) % NCHUNK;
    int b   = g2 / ((HH / 2) * NCHUNK);
    size_t base = ((size_t)(b * TT + ck * CHUNK)) * HH + 2 * hp;
    float2 P = make_float2(1.f, 1.f), S = make_float2(0.f, 0.f);
    #pragma unroll 8
    for (int t = 0; t < CHUNK; t++) {
        size_t idx = base + (size_t)t * HH;
        float2 z = __half22float2(*(const __half2*)(g_zh + idx));
        float2 c = __half22float2(*(const __half2*)(g_ch + idx));
        float ax = 1.f - z.x, ay = 1.f - z.y;
        S.x = ax * S.x + z.x * c.x;  P.x *= ax;
        S.y = ay * S.y + z.y * c.y;  P.y *= ay;
    }
    size_t o = ((size_t)(b * NCHUNK + ck)) * (HH / 2) + hp;
    ((float2*)g_P)[o] = P;
    ((float2*)g_S)[o] = S;
}

// ---------------------------------------------------------------------------
// Scan phase B: parallel Kogge-Stone over 64 chunk aggregates per (b,hid).
// ---------------------------------------------------------------------------
__global__ void scanB_kernel() {
    int gt   = blockIdx.x * blockDim.x + threadIdx.x;
    int lane = gt & 31;
    int wg   = gt >> 5;                 // 0..BB*HH-1
    int hid  = wg & (HH - 1);
    int b    = wg >> 10;                // HH = 1024
    int k0   = 2 * lane;
    size_t i0 = ((size_t)(b * NCHUNK + k0)) * HH + hid;
    float P0 = g_P[i0],      S0 = g_S[i0];
    float P1 = g_P[i0 + HH], S1 = g_S[i0 + HH];
    float cP = P1 * P0;
    float cS = P1 * S0 + S1;
    #pragma unroll
    for (int d = 1; d < 32; d <<= 1) {
        float pP = __shfl_up_sync(0xFFFFFFFFu, cP, d);
        float pS = __shfl_up_sync(0xFFFFFFFFu, cS, d);
        if (lane >= d) { cS = cP * pS + cS; cP = cP * pP; }
    }
    float eS = __shfl_up_sync(0xFFFFFFFFu, cS, 1);
    if (lane == 0) eS = 0.f;
    g_hin[i0]      = eS;
    g_hin[i0 + HH] = P0 * eS + S0;
}

// ---------------------------------------------------------------------------
// Scan phase C: re-run each chunk with the correct h_in, fuse residual +x.
// 2 hids/thread via half2/float2.
// ---------------------------------------------------------------------------
__global__ void scanC_kernel(const float* __restrict__ x, float* __restrict__ out) {
    int g2  = blockIdx.x * blockDim.x + threadIdx.x;   // over BB*NCHUNK*HH/2
    int hp  = g2 % (HH / 2);
    int ck  = (g2 / (HH / 2)) % NCHUNK;
    int b   = g2 / ((HH / 2) * NCHUNK);
    size_t base = ((size_t)(b * TT + ck * CHUNK)) * HH + 2 * hp;
    float2 h = ((const float2*)g_hin)[((size_t)(b * NCHUNK + ck)) * (HH / 2) + hp];
    #pragma unroll 8
    for (int t = 0; t < CHUNK; t++) {
        size_t idx = base + (size_t)t * HH;
        float2 z = __half22float2(*(const __half2*)(g_zh + idx));
        float2 c = __half22float2(*(const __half2*)(g_ch + idx));
        h.x = (1.f - z.x) * h.x + z.x * c.x;
        h.y = (1.f - z.y) * h.y + z.y * c.y;
        float2 xv = *(const float2*)(x + idx);
        *(float2*)(out + idx) = make_float2(h.x + xv.x, h.y + xv.y);
    }
}

// ---------------------------------------------------------------------------
extern "C" void kernel_launch(void* const* d_in, const int* in_sizes, int n_in,
                              void* d_out, int out_size) {
    const float* x     = (const float*)d_in[0];
    const float* gamma = (const float*)d_in[1];
    const float* beta  = (const float*)d_in[2];
    const float* Wg    = (const float*)d_in[3];
    const float* bg    = (const float*)d_in[4];
    const float* Wc    = (const float*)d_in[5];
    const float* bc    = (const float*)d_in[6];
    float* out = (float*)d_out;

    halfW_kernel<<<(2 * HH * HH / 4) / 256, 256>>>(Wg, Wc);
    ln_kernel<<<M_TOTAL / 8, 256>>>(x, gamma, beta);

    cudaFuncSetAttribute(gemm_kernel,
                         cudaFuncAttributeMaxDynamicSharedMemorySize, GEMM_SMEM);
    dim3 ggrid(2 * HH / BN, M_TOTAL / BM);   // (16, 128)
    gemm_kernel<<<ggrid, 128, GEMM_SMEM>>>(bg, bc);

    scanA_kernel<<<(BB * NCHUNK * HH / 2) / 256, 256>>>();
    scanB_kernel<<<(BB * HH * 32) / 256, 256>>>();
    scanC_kernel<<<(BB * NCHUNK * HH / 2) / 256, 256>>>(x, out);
}